// round 15
// baseline (speedup 1.0000x reference)
#include <cuda_runtime.h>
#include <stdint.h>

typedef unsigned long long u64;
typedef unsigned int u32;
typedef unsigned short u16;

#define B_IMG 8
#define N_PROP 2000
#define NCLS 91
#define NFG 90
#define NCAND (N_PROP*NFG)
#define K_TOP 2048
#define DETS 100
#define IMG_WF 1333.0f
#define IMG_HF 800.0f
#define SCORE_T 0.05f
#define NMS_T 0.5f
#define MIN_SZ 0.01f
#define XCLIP 4.135166556742356f
#define FILL_HI 0xBF800000u   /* == desc_key(-1.0f) */
#define KEY_CAP 12288
#define SMEM_SEL (98304 + 16384)   /* keybuf + skeys */
#define NWARP 4
#define GCAP 192
#define GW 6    /* GCAP/32 */

__device__ u64 g_keys[(size_t)B_IMG * NCAND];
__device__ int g_count[B_IMG];            // zero-init; reset by k_emit each call
__device__ float2 g_smax[B_IMG * N_PROP];
__device__ u64 g_skeys[B_IMG * K_TOP];
__device__ float4 g_cand_box[B_IMG * K_TOP];
__device__ __align__(8) unsigned char g_lab[B_IMG * K_TOP];  // bit7 = valid
__device__ u32 g_keep[B_IMG * 64];
__device__ u32 g_maxc[B_IMG];             // zero-init; reset by k_emit each call

// accurate expf, immune to --use_fast_math (~2 ulp).
__device__ __forceinline__ float exp_acc(float x){
    float j = fmaf(x, 1.442695041f, 12582912.0f) - 12582912.0f;
    float f = fmaf(j, -0.693145752f, x);
    f = fmaf(j, -1.42860677e-6f, f);
    float r =          1.37805939e-3f;
    r = fmaf(r, f, 8.37312452e-3f);
    r = fmaf(r, f, 4.16695364e-2f);
    r = fmaf(r, f, 1.66664720e-1f);
    r = fmaf(r, f, 4.99999851e-1f);
    r = fmaf(r, f, 1.0f);
    r = fmaf(r, f, 1.0f);
    int ji = (int)j;
    ji = ji < -252 ? -252 : (ji > 252 ? 252 : ji);
    int j1 = ji >> 1;
    int j2 = ji - j1;
    float s1 = __int_as_float((127 + j1) << 23);
    float s2 = __int_as_float((127 + j2) << 23);
    return r * s1 * s2;
}

// higher score -> smaller key
__device__ __forceinline__ u32 desc_key(float f){
    u32 u = __float_as_uint(f);
    u = (u & 0x80000000u) ? ~u : (u | 0x80000000u);
    return ~u;
}

// order-preserving float<->int map (no NaNs in data)
__device__ __forceinline__ int f2ord(float f){
    int i = __float_as_int(f);
    return i ^ ((i >> 31) & 0x7FFFFFFF);
}
__device__ __forceinline__ float ord2f(int m){
    return __int_as_float(m ^ ((m >> 31) & 0x7FFFFFFF));
}

__device__ __forceinline__ bool decode_box(float4 p, float4 r, float4& bx){
    float w  = p.z - p.x, h  = p.w - p.y;
    float cx = p.x + 0.5f*w, cy = p.y + 0.5f*h;
    float dx = __fdiv_rn(r.x, 10.0f), dy = __fdiv_rn(r.y, 10.0f);
    float dw = fminf(__fdiv_rn(r.z, 5.0f), XCLIP);
    float dh = fminf(__fdiv_rn(r.w, 5.0f), XCLIP);
    float pcx = dx*w + cx, pcy = dy*h + cy;
    float pw = exp_acc(dw)*w, ph = exp_acc(dh)*h;
    bx.x = fminf(fmaxf(pcx - 0.5f*pw, 0.0f), IMG_WF);
    bx.y = fminf(fmaxf(pcy - 0.5f*ph, 0.0f), IMG_HF);
    bx.z = fminf(fmaxf(pcx + 0.5f*pw, 0.0f), IMG_WF);
    bx.w = fminf(fmaxf(pcy + 0.5f*ph, 0.0f), IMG_HF);
    return ((bx.z - bx.x) >= MIN_SZ) && ((bx.w - bx.y) >= MIN_SZ);
}

__device__ __forceinline__ bool cand_full(int img, int idx,
        const float* __restrict__ logits, const float4* __restrict__ regs4,
        const float4* __restrict__ props4, float& score, float4& bx){
    int i_local = idx / NFG;
    int c = idx - i_local*NFG + 1;
    int i = img*N_PROP + i_local;
    float2 md = g_smax[i];
    float l = logits[(size_t)i*NCLS + c];
    score = __fdiv_rn(exp_acc(l - md.x), md.y);
    bool szok = decode_box(props4[i], regs4[(size_t)i*NCLS + c], bx);
    return (score > SCORE_T) && szok;
}

__global__ void __launch_bounds__(256) k_score(const float* __restrict__ logits,
                        const float4* __restrict__ regs4,
                        const float4* __restrict__ props4){
    __shared__ int s_cnt, s_base;
    int warp = threadIdx.x >> 5, lane = threadIdx.x & 31;
    int p = blockIdx.x*8 + warp;
    int img = p / N_PROP;
    int i_local = p - img*N_PROP;
    if (threadIdx.x == 0) s_cnt = 0;
    __syncthreads();
    const float* lrow = logits + (size_t)p*NCLS;
    float l0 = lrow[lane];
    float l1 = lrow[lane+32];
    float l2 = (lane < NCLS-64) ? lrow[lane+64] : -3.0e38f;
    float m3 = fmaxf(fmaxf(l0,l1), l2);
    float m = ord2f(__reduce_max_sync(0xFFFFFFFFu, f2ord(m3)));
    float e0 = exp_acc(l0-m), e1 = exp_acc(l1-m);
    float e2 = (lane < NCLS-64) ? exp_acc(l2-m) : 0.0f;
    float s = e0+e1+e2;
    #pragma unroll
    for (int o=16;o;o>>=1) s += __shfl_xor_sync(0xFFFFFFFFu, s, o);
    if (lane == 0) g_smax[p] = make_float2(m, s);
    float th = (SCORE_T * s) * (1.0f - 2e-6f);
    float4 pr = props4[p];
    u64 karr[3]; int cnt = 0;
    #pragma unroll
    for (int slot=0; slot<3; slot++){
        int c = lane + slot*32;
        float e = (slot==0) ? e0 : ((slot==1) ? e1 : e2);
        if (c >= 1 && c < NCLS && e > th){
            float score = __fdiv_rn(e, s);
            if (score > SCORE_T){
                float4 bx;
                if (decode_box(pr, regs4[(size_t)p*NCLS + c], bx)){
                    u32 hi = desc_key(score);
                    karr[cnt++] = (((u64)hi) << 32)
                                | (u32)(i_local*NFG + (c-1));
                }
            }
        }
    }
    int tot = cnt;
    #pragma unroll
    for (int o=16;o;o>>=1) tot += __shfl_xor_sync(0xFFFFFFFFu, tot, o);
    int my = cnt;
    #pragma unroll
    for (int o=1;o<32;o<<=1){ int v=__shfl_up_sync(0xFFFFFFFFu,my,o); if(lane>=o) my+=v; }
    int wbase = 0;
    if (lane == 0 && tot) wbase = atomicAdd(&s_cnt, tot);
    wbase = __shfl_sync(0xFFFFFFFFu, wbase, 0);
    int pos = wbase + my - cnt;
    __syncthreads();
    if (threadIdx.x == 0) s_base = atomicAdd(&g_count[img], s_cnt);
    __syncthreads();
    for (int k2=0; k2<cnt; k2++)
        g_keys[(size_t)img*NCAND + s_base + pos + k2] = karr[k2];
}

// register compare-exchange for bitonic stages j<=16 (in-warp)
__device__ __forceinline__ u64 cmpex(u64 v, int j, bool up){
    u64 p = __shfl_xor_sync(0xFFFFFFFFu, v, j);
    bool lower = ((threadIdx.x & j) == 0);
    u64 mn = v < p ? v : p;
    u64 mx = v < p ? p : v;
    return (lower == up) ? mn : mx;
}

__global__ void __launch_bounds__(1024) k_select(const float* __restrict__ logits,
                         const float4* __restrict__ regs4,
                         const float4* __restrict__ props4){
    extern __shared__ char dsm[];
    u64* keybuf = (u64*)dsm;                  // 96KB
    u64* skeys  = (u64*)(dsm + 98304);        // 16KB

    __shared__ u32 hist[256];
    __shared__ u32 hist8[8][256];
    __shared__ int wsum[32];
    __shared__ int s_digit, s_below, s_app, s_comp;

    int img = blockIdx.x, tid = threadIdx.x;
    int warp = tid >> 5, lane = tid & 31;
    u64* buf = g_keys + (size_t)img*NCAND;
    int n0 = g_count[img];
    int n = n0;

    // ---- degenerate fill path (count < K_TOP): append invalids in index order
    if (n0 < K_TOP){
        if (tid == 0) s_app = 0;
        __syncthreads();
        for (int base = 0; base < NCAND; base += 1024){
            if (s_app >= K_TOP - n0) break;
            int idx = base + tid;
            bool flag = false;
            if (idx < NCAND){
                float sc; float4 bx;
                flag = !cand_full(img, idx, logits, regs4, props4, sc, bx);
            }
            u32 bal = __ballot_sync(0xFFFFFFFFu, flag);
            if (lane == 0) wsum[warp] = __popc(bal);
            __syncthreads();
            int off = 0, total = 0;
            #pragma unroll
            for (int wk = 0; wk < 32; wk++){ int v = wsum[wk]; if (wk < warp) off += v; total += v; }
            int rank = off + __popc(bal & ((1u<<lane)-1u));
            int need = K_TOP - n0 - s_app;
            if (flag && rank < need)
                buf[n0 + s_app + rank] = (((u64)FILL_HI)<<32) | (u32)idx;
            __syncthreads();
            if (tid == 0) s_app += (total < need ? total : need);
            __syncthreads();
        }
        n = K_TOP;
        __syncthreads();
    }

    int nloop = (n + 1023) & ~1023;

    bool insm = (n <= KEY_CAP);
    if (insm){
        for (int j = tid; j < n; j += 1024) keybuf[j] = buf[j];
        __syncthreads();
    }
    const u64* kb = insm ? (const u64*)keybuf : (const u64*)buf;

    // ---- exact K_TOP-th key via MSB radix select, 7 passes (byte at shift 24
    // is always zero).  After pass 2 (16 bits fixed) the surviving keys are
    // compacted into skeys so passes 3-7 scan only survivors (usually ~tens).
    u64 T = ~0ull;
    if (n > K_TOP){
        const int shifts[7] = {56, 48, 40, 32, 16, 8, 0};
        u64 prefix = 0, himask = 0;
        u32 kk = K_TOP;
        const u64* src = kb;
        int m = n;
        for (int pass = 0; pass < 7; pass++){
            int shift = shifts[pass];
            for (int d = tid; d < 2048; d += 1024) ((u32*)hist8)[d] = 0u;
            __syncthreads();
            for (int jj = tid; jj < m; jj += 1024){
                u64 key = src[jj];
                if ((key & himask) == prefix)
                    atomicAdd(&hist8[warp>>2][(u32)(key>>shift)&255u], 1u);
            }
            __syncthreads();
            if (tid < 256){
                u32 sum = 0;
                #pragma unroll
                for (int gg = 0; gg < 8; gg++) sum += hist8[gg][tid];
                hist[tid] = sum;
            }
            __syncthreads();
            if (warp == 0){
                u32 loc[8], sum = 0;
                #pragma unroll
                for (int r = 0; r < 8; r++){ loc[r] = hist[lane*8+r]; sum += loc[r]; }
                u32 inc = sum;
                #pragma unroll
                for (int o = 1; o < 32; o <<= 1){
                    u32 v = __shfl_up_sync(0xFFFFFFFFu, inc, o);
                    if (lane >= o) inc += v;
                }
                u32 excl = inc - sum;
                if (kk > excl && kk <= inc){
                    u32 cum = excl;
                    #pragma unroll
                    for (int r = 0; r < 8; r++){
                        if (cum + loc[r] >= kk){ s_digit = lane*8+r; s_below = (int)cum; break; }
                        cum += loc[r];
                    }
                }
            }
            __syncthreads();
            prefix |= ((u64)(u32)s_digit) << shift;
            kk -= (u32)s_below;
            himask = (~0ull) << shift;
            __syncthreads();

            // progressive compaction: after 16 prefix bits are fixed,
            // survivors (count = hist[s_digit]) almost always fit in skeys.
            if (pass == 1){
                if (tid == 0) s_comp = 0;
                __syncthreads();
                int mloop = (m + 1023) & ~1023;
                for (int jj = tid; jj < mloop; jj += 1024){
                    bool inb = (jj < m);
                    u64 key = inb ? src[jj] : 0ull;
                    bool sel = inb && ((key & himask) == prefix);
                    u32 bal = __ballot_sync(0xFFFFFFFFu, sel);
                    int base = 0;
                    if (lane == 0 && bal) base = atomicAdd(&s_comp, __popc(bal));
                    base = __shfl_sync(0xFFFFFFFFu, base, 0);
                    if (sel){
                        int pp = base + __popc(bal & ((1u<<lane)-1u));
                        if (pp < K_TOP) skeys[pp] = key;
                    }
                }
                __syncthreads();
                if (s_comp <= K_TOP){ src = skeys; m = s_comp; }
                __syncthreads();
            }
        }
        T = prefix;
    }

    // ---- compact exactly K_TOP keys (warp-aggregated, padded loop)
    if (tid == 0) s_comp = 0;
    __syncthreads();
    for (int jj = tid; jj < nloop; jj += 1024){
        bool inb = (jj < n);
        u64 key = inb ? kb[jj] : ~0ull;
        bool sel = inb && (key <= T);
        u32 bal = __ballot_sync(0xFFFFFFFFu, sel);
        int base = 0;
        if (lane == 0 && bal) base = atomicAdd(&s_comp, __popc(bal));
        base = __shfl_sync(0xFFFFFFFFu, base, 0);
        if (sel){
            int pp = base + __popc(bal & ((1u<<lane)-1u));
            if (pp < K_TOP) skeys[pp] = key;
        }
    }
    __syncthreads();

    // ---- bitonic sort 2048 keys
    {
        u64 a = skeys[tid], b = skeys[tid + 1024];
        #pragma unroll
        for (int k = 2; k <= 32; k <<= 1){
            bool upa = ((tid & k) == 0);
            bool upb = (((tid + 1024) & k) == 0);
            #pragma unroll
            for (int j = k >> 1; j >= 1; j >>= 1){
                a = cmpex(a, j, upa);
                b = cmpex(b, j, upb);
            }
        }
        skeys[tid] = a; skeys[tid + 1024] = b;
        __syncthreads();
        for (int k = 64; k <= K_TOP; k <<= 1){
            for (int j = k >> 1; j >= 32; j >>= 1){
                int ii = ((tid & ~(j-1)) << 1) | (tid & (j-1));
                int pp = ii | j;
                bool up = ((ii & k) == 0);
                u64 x = skeys[ii], y = skeys[pp];
                if ((x > y) == up){ skeys[ii] = y; skeys[pp] = x; }
                __syncthreads();
            }
            a = skeys[tid]; b = skeys[tid + 1024];
            bool upa = ((tid & k) == 0);
            bool upb = (((tid + 1024) & k) == 0);
            #pragma unroll
            for (int j = 16; j >= 1; j >>= 1){
                a = cmpex(a, j, upa);
                b = cmpex(b, j, upb);
            }
            skeys[tid] = a; skeys[tid + 1024] = b;
            __syncthreads();
        }
    }

    // ---- fused decode: skeys still in smem; decode both halves
    u32 lmax = 0u;
    #pragma unroll
    for (int half = 0; half < 2; half++){
        int s = tid + half*1024;
        u64 key = skeys[s];
        g_skeys[img*K_TOP + s] = key;
        u32 hi = (u32)(key >> 32);
        int idx = (int)(key & 0xFFFFFFFFull);
        int il = idx / NFG;
        int c = idx - il*NFG + 1;
        int i = img*N_PROP + il;
        float4 bx;
        decode_box(props4[i], regs4[(size_t)i*NCLS + c], bx);
        g_cand_box[img*K_TOP + s] = bx;
        bool valid = (hi != FILL_HI);
        g_lab[img*K_TOP + s] = (unsigned char)(c | (valid ? 0x80 : 0));
        u32 vb = __ballot_sync(0xFFFFFFFFu, valid);
        if (lane == 0) g_keep[img*64 + (s>>5)] = vb;
        float mx = fmaxf(fmaxf(bx.x, bx.y), fmaxf(bx.z, bx.w));
        u32 mxu = __float_as_uint(mx);
        lmax = lmax > mxu ? lmax : mxu;
    }
    #pragma unroll
    for (int o = 16; o; o >>= 1){
        u32 v = __shfl_xor_sync(0xFFFFFFFFu, lmax, o);
        lmax = lmax > v ? lmax : v;
    }
    if (lane == 0) atomicMax(&g_maxc[img], lmax);
}

// 4 warps/block, one warp per (image,label).
// Suppression-matrix greedy: parallel IoU mask build, then bit-only serial scan.
__global__ void __launch_bounds__(NWARP*32) k_nms(){
    __shared__ u16 mem[NWARP][K_TOP];
    __shared__ u32 smask[NWARP][GCAP][GW];
    __shared__ u32 kb[NWARP][64];
    int wwarp = threadIdx.x >> 5, lane = threadIdx.x & 31;
    int pair = blockIdx.x*NWARP + wwarp;
    int img = pair / NFG;
    int lab = pair - img*NFG + 1;
    u16* memw = mem[wwarp];
    u32* kbw = kb[wwarp];
    float mul = __uint_as_float(g_maxc[img]) + 1.0f;
    float off = (float)lab * mul;
    const u64* labp8 = (const u64*)(g_lab + img*K_TOP);
    const unsigned char* labp = g_lab + img*K_TOP;
    const float4* boxp = g_cand_box + img*K_TOP;

    int g = 0;
    #pragma unroll
    for (int it = 0; it < 8; it++){
        u64 v = labp8[it*32 + lane];
        u32 mymask = 0;
        #pragma unroll
        for (int k = 0; k < 8; k++){
            if ((((u32)(v >> (8*k))) & 0x7Fu) == (u32)lab) mymask |= (1u<<k);
        }
        int mycnt = __popc(mymask);
        int inc = mycnt;
        #pragma unroll
        for (int o=1;o<32;o<<=1){ int x=__shfl_up_sync(0xFFFFFFFFu,inc,o); if(lane>=o) inc+=x; }
        int pos = g + inc - mycnt;
        int tb = (it*32 + lane)*8;
        #pragma unroll
        for (int k = 0; k < 8; k++){
            if (mymask & (1u<<k)) memw[pos++] = (u16)(tb + k);
        }
        g += __shfl_sync(0xFFFFFFFFu, inc, 31);
    }
    __syncwarp();
    int gpad = (g + 31) & ~31;
    for (int ch = 0; ch < gpad; ch += 32){
        int j = ch + lane;
        bool val = (j < g) ? ((labp[memw[j]] & 0x80u) != 0) : false;
        u32 bal = __ballot_sync(0xFFFFFFFFu, val);
        if (lane == 0) kbw[ch>>5] = bal;
    }
    __syncwarp();

    if (g <= GCAP){
        int gwords = (g + 31) >> 5;
        for (int i = lane; i < g; i += 32){
            float4 bi = boxp[memw[i]];
            float ax = bi.x + off, ay = bi.y + off, az = bi.z + off, aw = bi.w + off;
            float aa = (az - ax) * (aw - ay);
            for (int w = 0; w < gwords; w++){
                u32 bits = 0u;
                int j0 = w << 5;
                int jend = min(g, j0 + 32);
                for (int j = max(j0, i+1); j < jend; j++){
                    float4 bj = boxp[memw[j]];
                    float ox = bj.x + off, oy = bj.y + off, oz = bj.z + off, ow = bj.w + off;
                    float ab = (oz - ox) * (ow - oy);
                    float ltx = fmaxf(ax, ox), lty = fmaxf(ay, oy);
                    float rbx = fminf(az, oz), rby = fminf(aw, ow);
                    float wx = fmaxf(rbx - ltx, 0.0f), wy = fmaxf(rby - lty, 0.0f);
                    float inter = wx * wy;
                    float iou = __fdiv_rn(inter, aa + ab - inter);
                    if (iou > NMS_T) bits |= 1u << (j - j0);
                }
                smask[wwarp][i][w] = bits;
            }
        }
        __syncwarp();
        u32 kw = (lane < gwords) ? kbw[lane] : 0u;
        for (int i = 0; i < g; i++){
            u32 wi = __shfl_sync(0xFFFFFFFFu, kw, i >> 5);
            if ((wi >> (i & 31)) & 1u){
                if (lane < gwords) kw &= ~smask[wwarp][i][lane];
            }
        }
        if (lane < gwords) kbw[lane] = kw;
        __syncwarp();
    } else {
        for (int i = 0; i < g; i++){
            if (!((kbw[i>>5] >> (i&31)) & 1u)) continue;
            float4 bi = boxp[memw[i]];
            float ax = bi.x + off, ay = bi.y + off, az = bi.z + off, aw = bi.w + off;
            float aa = (az - ax) * (aw - ay);
            for (int j = i + 1 + lane; j < g; j += 32){
                float4 bj = boxp[memw[j]];
                float ox = bj.x + off, oy = bj.y + off, oz = bj.z + off, ow = bj.w + off;
                float ab = (oz - ox) * (ow - oy);
                float ltx = fmaxf(ax, ox), lty = fmaxf(ay, oy);
                float rbx = fminf(az, oz), rby = fminf(aw, ow);
                float wx = fmaxf(rbx - ltx, 0.0f), wy = fmaxf(rby - lty, 0.0f);
                float inter = wx * wy;
                float iou = __fdiv_rn(inter, aa + ab - inter);
                if (iou > NMS_T) atomicAnd(&kbw[j>>5], ~(1u<<(j&31)));
            }
            __syncwarp();
        }
    }

    for (int j = lane; j < g; j += 32){
        if (!((kbw[j>>5] >> (j&31)) & 1u)){
            int t = memw[j];
            atomicAnd(&g_keep[img*64 + (t>>5)], ~(1u<<(t&31)));
        }
    }
}

__global__ void __launch_bounds__(256) k_emit(float* __restrict__ out){
    __shared__ u32 s_keep[64];
    __shared__ int s_wbase[64];
    __shared__ int s_tot;
    int img = blockIdx.x, tid = threadIdx.x;
    int warp = tid >> 5, lane = tid & 31;
    if (tid < 64) s_keep[tid] = g_keep[img*64 + tid];
    __syncthreads();
    if (warp == 0){
        u32 w0 = s_keep[lane];
        int c0 = __popc(w0), sc0 = c0;
        #pragma unroll
        for (int o=1;o<32;o<<=1){ int v=__shfl_up_sync(0xFFFFFFFFu,sc0,o); if(lane>=o) sc0+=v; }
        s_wbase[lane] = sc0 - c0;
        int tot0 = __shfl_sync(0xFFFFFFFFu, sc0, 31);
        u32 w1 = s_keep[32+lane];
        int c1 = __popc(w1), sc1 = c1;
        #pragma unroll
        for (int o=1;o<32;o<<=1){ int v=__shfl_up_sync(0xFFFFFFFFu,sc1,o); if(lane>=o) sc1+=v; }
        s_wbase[32+lane] = tot0 + sc1 - c1;
        if (lane == 31) s_tot = tot0 + sc1;
    }
    __syncthreads();
    int K = s_tot;
    for (int t2 = tid; t2 < K_TOP; t2 += 256){
        u32 w = s_keep[t2>>5];
        int kbefore = s_wbase[t2>>5] + __popc(w & ((1u<<(t2&31))-1u));
        bool kept = (w >> (t2&31)) & 1u;
        int slot = -1; float osc = 0.0f;
        if (kept){
            if (kbefore < DETS){
                slot = kbefore;
                u32 hi = (u32)(g_skeys[img*K_TOP + t2] >> 32);
                osc = __uint_as_float(~hi & 0x7FFFFFFFu);
            }
        } else if (K < DETS){
            int s2 = K + (t2 - kbefore);
            if (s2 < DETS){ slot = s2; osc = -1.0f; }
        }
        if (slot >= 0){
            ((float4*)out)[img*DETS + slot] = g_cand_box[img*K_TOP + t2];
            out[B_IMG*DETS*4 + img*DETS + slot] = osc;
            out[B_IMG*DETS*5 + img*DETS + slot] = (float)(g_lab[img*K_TOP + t2] & 0x7F);
        }
    }
    __syncthreads();
    if (tid == 0){ g_count[img] = 0; g_maxc[img] = 0u; }
}

extern "C" void kernel_launch(void* const* d_in, const int* in_sizes, int n_in,
                              void* d_out, int out_size) {
    const float*  logits = (const float*)d_in[0];
    const float4* regs4  = (const float4*)d_in[1];
    const float4* props4 = (const float4*)d_in[2];
    float* out = (float*)d_out;
    cudaFuncSetAttribute(k_select, cudaFuncAttributeMaxDynamicSharedMemorySize, SMEM_SEL);
    k_score<<<(B_IMG*N_PROP)/8, 256>>>(logits, regs4, props4);
    k_select<<<B_IMG, 1024, SMEM_SEL>>>(logits, regs4, props4);
    k_nms<<<(B_IMG*NFG)/NWARP, NWARP*32>>>();
    k_emit<<<B_IMG, 256>>>(out);
}

// round 16
// speedup vs baseline: 1.0298x; 1.0298x over previous
#include <cuda_runtime.h>
#include <stdint.h>

typedef unsigned long long u64;
typedef unsigned int u32;
typedef unsigned short u16;

#define B_IMG 8
#define N_PROP 2000
#define NCLS 91
#define NFG 90
#define NCAND (N_PROP*NFG)
#define K_TOP 2048
#define DETS 100
#define IMG_WF 1333.0f
#define IMG_HF 800.0f
#define SCORE_T 0.05f
#define NMS_T 0.5f
#define MIN_SZ 0.01f
#define XCLIP 4.135166556742356f
#define FILL_HI 0xBF800000u   /* == desc_key(-1.0f) */
#define KEY_CAP 12288
#define SMEM_SEL (98304 + 16384)   /* keybuf + skeys */
#define NWARP 4
#define GCAP 192
#define GW 6    /* GCAP/32 */

__device__ u64 g_keys[(size_t)B_IMG * NCAND];
__device__ int g_count[B_IMG];            // zero-init; reset by k_emit each call
__device__ float2 g_smax[B_IMG * N_PROP];
__device__ u64 g_skeys[B_IMG * K_TOP];
__device__ float4 g_cand_box[B_IMG * K_TOP];
__device__ __align__(8) unsigned char g_lab[B_IMG * K_TOP];  // bit7 = valid
__device__ u32 g_keep[B_IMG * 64];
__device__ u32 g_maxc[B_IMG];             // zero-init; reset by k_emit each call

// accurate expf, immune to --use_fast_math (~2 ulp).
__device__ __forceinline__ float exp_acc(float x){
    float j = fmaf(x, 1.442695041f, 12582912.0f) - 12582912.0f;
    float f = fmaf(j, -0.693145752f, x);
    f = fmaf(j, -1.42860677e-6f, f);
    float r =          1.37805939e-3f;
    r = fmaf(r, f, 8.37312452e-3f);
    r = fmaf(r, f, 4.16695364e-2f);
    r = fmaf(r, f, 1.66664720e-1f);
    r = fmaf(r, f, 4.99999851e-1f);
    r = fmaf(r, f, 1.0f);
    r = fmaf(r, f, 1.0f);
    int ji = (int)j;
    ji = ji < -252 ? -252 : (ji > 252 ? 252 : ji);
    int j1 = ji >> 1;
    int j2 = ji - j1;
    float s1 = __int_as_float((127 + j1) << 23);
    float s2 = __int_as_float((127 + j2) << 23);
    return r * s1 * s2;
}

// higher score -> smaller key
__device__ __forceinline__ u32 desc_key(float f){
    u32 u = __float_as_uint(f);
    u = (u & 0x80000000u) ? ~u : (u | 0x80000000u);
    return ~u;
}

// order-preserving float<->int map (no NaNs in data)
__device__ __forceinline__ int f2ord(float f){
    int i = __float_as_int(f);
    return i ^ ((i >> 31) & 0x7FFFFFFF);
}
__device__ __forceinline__ float ord2f(int m){
    return __int_as_float(m ^ ((m >> 31) & 0x7FFFFFFF));
}

__device__ __forceinline__ bool decode_box(float4 p, float4 r, float4& bx){
    float w  = p.z - p.x, h  = p.w - p.y;
    float cx = p.x + 0.5f*w, cy = p.y + 0.5f*h;
    float dx = __fdiv_rn(r.x, 10.0f), dy = __fdiv_rn(r.y, 10.0f);
    float dw = fminf(__fdiv_rn(r.z, 5.0f), XCLIP);
    float dh = fminf(__fdiv_rn(r.w, 5.0f), XCLIP);
    float pcx = dx*w + cx, pcy = dy*h + cy;
    float pw = exp_acc(dw)*w, ph = exp_acc(dh)*h;
    bx.x = fminf(fmaxf(pcx - 0.5f*pw, 0.0f), IMG_WF);
    bx.y = fminf(fmaxf(pcy - 0.5f*ph, 0.0f), IMG_HF);
    bx.z = fminf(fmaxf(pcx + 0.5f*pw, 0.0f), IMG_WF);
    bx.w = fminf(fmaxf(pcy + 0.5f*ph, 0.0f), IMG_HF);
    return ((bx.z - bx.x) >= MIN_SZ) && ((bx.w - bx.y) >= MIN_SZ);
}

__device__ __forceinline__ bool cand_full(int img, int idx,
        const float* __restrict__ logits, const float4* __restrict__ regs4,
        const float4* __restrict__ props4, float& score, float4& bx){
    int i_local = idx / NFG;
    int c = idx - i_local*NFG + 1;
    int i = img*N_PROP + i_local;
    float2 md = g_smax[i];
    float l = logits[(size_t)i*NCLS + c];
    score = __fdiv_rn(exp_acc(l - md.x), md.y);
    bool szok = decode_box(props4[i], regs4[(size_t)i*NCLS + c], bx);
    return (score > SCORE_T) && szok;
}

// approximate-but-conservative validity: abs error on clipped coords < 0.015,
// so ws_a > 0.04 guarantees exact ws >= 0.01.  Uncertain band -> exact path.
__device__ __forceinline__ bool valid_fastpath(float4 p, float4 r){
    float w  = p.z - p.x, h  = p.w - p.y;
    float cx = p.x + 0.5f*w, cy = p.y + 0.5f*h;
    float dxa = r.x*0.1f, dya = r.y*0.1f;
    float dwa = fminf(r.z*0.2f, XCLIP);
    float dha = fminf(r.w*0.2f, XCLIP);
    float pcxa = dxa*w + cx, pcya = dya*h + cy;
    float pwa = __expf(dwa)*w, pha = __expf(dha)*h;
    float x1 = fminf(fmaxf(pcxa - 0.5f*pwa, 0.0f), IMG_WF);
    float y1 = fminf(fmaxf(pcya - 0.5f*pha, 0.0f), IMG_HF);
    float x2 = fminf(fmaxf(pcxa + 0.5f*pwa, 0.0f), IMG_WF);
    float y2 = fminf(fmaxf(pcya + 0.5f*pha, 0.0f), IMG_HF);
    float wsa = x2 - x1, hsa = y2 - y1;
    if (wsa > 0.04f && hsa > 0.04f) return true;     // provably valid
    float4 bx;
    return decode_box(p, r, bx);                     // exact fallback
}

__global__ void __launch_bounds__(256) k_score(const float* __restrict__ logits,
                        const float4* __restrict__ regs4,
                        const float4* __restrict__ props4){
    __shared__ int s_cnt, s_base;
    int warp = threadIdx.x >> 5, lane = threadIdx.x & 31;
    int p = blockIdx.x*8 + warp;
    int img = p / N_PROP;
    int i_local = p - img*N_PROP;
    if (threadIdx.x == 0) s_cnt = 0;
    __syncthreads();
    const float* lrow = logits + (size_t)p*NCLS;
    float l0 = lrow[lane];
    float l1 = lrow[lane+32];
    float l2 = (lane < NCLS-64) ? lrow[lane+64] : -3.0e38f;
    float m3 = fmaxf(fmaxf(l0,l1), l2);
    float m = ord2f(__reduce_max_sync(0xFFFFFFFFu, f2ord(m3)));
    float e0 = exp_acc(l0-m), e1 = exp_acc(l1-m);
    float e2 = (lane < NCLS-64) ? exp_acc(l2-m) : 0.0f;
    float s = e0+e1+e2;
    #pragma unroll
    for (int o=16;o;o>>=1) s += __shfl_xor_sync(0xFFFFFFFFu, s, o);
    if (lane == 0) g_smax[p] = make_float2(m, s);
    // conservative prefilter: e <= th  ==>  fl(e/s) <= 0.05 guaranteed.
    float th = (SCORE_T * s) * (1.0f - 2e-6f);
    float4 pr = props4[p];
    u64 karr[3]; int cnt = 0;
    #pragma unroll
    for (int slot=0; slot<3; slot++){
        int c = lane + slot*32;
        float e = (slot==0) ? e0 : ((slot==1) ? e1 : e2);
        if (c >= 1 && c < NCLS && e > th){
            float score = __fdiv_rn(e, s);
            if (score > SCORE_T){
                if (valid_fastpath(pr, regs4[(size_t)p*NCLS + c])){
                    u32 hi = desc_key(score);
                    karr[cnt++] = (((u64)hi) << 32)
                                | (u32)(i_local*NFG + (c-1));
                }
            }
        }
    }
    int my = cnt;
    #pragma unroll
    for (int o=1;o<32;o<<=1){ int v=__shfl_up_sync(0xFFFFFFFFu,my,o); if(lane>=o) my+=v; }
    int tot = __shfl_sync(0xFFFFFFFFu, my, 31);
    int wbase = 0;
    if (lane == 0 && tot) wbase = atomicAdd(&s_cnt, tot);
    wbase = __shfl_sync(0xFFFFFFFFu, wbase, 0);
    int pos = wbase + my - cnt;
    __syncthreads();
    if (threadIdx.x == 0) s_base = atomicAdd(&g_count[img], s_cnt);
    __syncthreads();
    for (int k2=0; k2<cnt; k2++)
        g_keys[(size_t)img*NCAND + s_base + pos + k2] = karr[k2];
}

// register compare-exchange for bitonic stages j<=16 (in-warp)
__device__ __forceinline__ u64 cmpex(u64 v, int j, bool up){
    u64 p = __shfl_xor_sync(0xFFFFFFFFu, v, j);
    bool lower = ((threadIdx.x & j) == 0);
    u64 mn = v < p ? v : p;
    u64 mx = v < p ? p : v;
    return (lower == up) ? mn : mx;
}

__global__ void __launch_bounds__(1024) k_select(const float* __restrict__ logits,
                         const float4* __restrict__ regs4,
                         const float4* __restrict__ props4){
    extern __shared__ char dsm[];
    u64* keybuf = (u64*)dsm;                  // 96KB
    u64* skeys  = (u64*)(dsm + 98304);        // 16KB

    __shared__ u32 hist[256];
    __shared__ u32 hist8[8][256];
    __shared__ int wsum[32];
    __shared__ int s_digit, s_below, s_app, s_comp;

    int img = blockIdx.x, tid = threadIdx.x;
    int warp = tid >> 5, lane = tid & 31;
    u64* buf = g_keys + (size_t)img*NCAND;
    int n0 = g_count[img];
    int n = n0;

    // ---- degenerate fill path (count < K_TOP): append invalids in index order
    if (n0 < K_TOP){
        if (tid == 0) s_app = 0;
        __syncthreads();
        for (int base = 0; base < NCAND; base += 1024){
            if (s_app >= K_TOP - n0) break;
            int idx = base + tid;
            bool flag = false;
            if (idx < NCAND){
                float sc; float4 bx;
                flag = !cand_full(img, idx, logits, regs4, props4, sc, bx);
            }
            u32 bal = __ballot_sync(0xFFFFFFFFu, flag);
            if (lane == 0) wsum[warp] = __popc(bal);
            __syncthreads();
            int off = 0, total = 0;
            #pragma unroll
            for (int wk = 0; wk < 32; wk++){ int v = wsum[wk]; if (wk < warp) off += v; total += v; }
            int rank = off + __popc(bal & ((1u<<lane)-1u));
            int need = K_TOP - n0 - s_app;
            if (flag && rank < need)
                buf[n0 + s_app + rank] = (((u64)FILL_HI)<<32) | (u32)idx;
            __syncthreads();
            if (tid == 0) s_app += (total < need ? total : need);
            __syncthreads();
        }
        n = K_TOP;
        __syncthreads();
    }

    int nloop = (n + 1023) & ~1023;

    bool insm = (n <= KEY_CAP);
    if (insm){
        for (int j = tid; j < n; j += 1024) keybuf[j] = buf[j];
        __syncthreads();
    }
    const u64* kb = insm ? (const u64*)keybuf : (const u64*)buf;

    // ---- exact K_TOP-th key via MSB radix select, 7 passes
    u64 T = ~0ull;
    if (n > K_TOP){
        const int shifts[7] = {56, 48, 40, 32, 16, 8, 0};
        u64 prefix = 0, himask = 0;
        u32 kk = K_TOP;
        for (int pass = 0; pass < 7; pass++){
            int shift = shifts[pass];
            for (int d = tid; d < 2048; d += 1024) ((u32*)hist8)[d] = 0u;
            __syncthreads();
            for (int jj = tid; jj < n; jj += 1024){
                u64 key = kb[jj];
                if ((key & himask) == prefix)
                    atomicAdd(&hist8[warp>>2][(u32)(key>>shift)&255u], 1u);
            }
            __syncthreads();
            if (tid < 256){
                u32 sum = 0;
                #pragma unroll
                for (int gg = 0; gg < 8; gg++) sum += hist8[gg][tid];
                hist[tid] = sum;
            }
            __syncthreads();
            if (warp == 0){
                u32 loc[8], sum = 0;
                #pragma unroll
                for (int r = 0; r < 8; r++){ loc[r] = hist[lane*8+r]; sum += loc[r]; }
                u32 inc = sum;
                #pragma unroll
                for (int o = 1; o < 32; o <<= 1){
                    u32 v = __shfl_up_sync(0xFFFFFFFFu, inc, o);
                    if (lane >= o) inc += v;
                }
                u32 excl = inc - sum;
                if (kk > excl && kk <= inc){
                    u32 cum = excl;
                    #pragma unroll
                    for (int r = 0; r < 8; r++){
                        if (cum + loc[r] >= kk){ s_digit = lane*8+r; s_below = (int)cum; break; }
                        cum += loc[r];
                    }
                }
            }
            __syncthreads();
            prefix |= ((u64)(u32)s_digit) << shift;
            kk -= (u32)s_below;
            himask = (~0ull) << shift;
            __syncthreads();
        }
        T = prefix;
    }

    // ---- compact exactly K_TOP keys (warp-aggregated, padded loop)
    if (tid == 0) s_comp = 0;
    __syncthreads();
    for (int jj = tid; jj < nloop; jj += 1024){
        bool inb = (jj < n);
        u64 key = inb ? kb[jj] : ~0ull;
        bool sel = inb && (key <= T);
        u32 bal = __ballot_sync(0xFFFFFFFFu, sel);
        int base = 0;
        if (lane == 0 && bal) base = atomicAdd(&s_comp, __popc(bal));
        base = __shfl_sync(0xFFFFFFFFu, base, 0);
        if (sel){
            int pp = base + __popc(bal & ((1u<<lane)-1u));
            if (pp < K_TOP) skeys[pp] = key;
        }
    }
    __syncthreads();

    // ---- bitonic sort 2048 keys
    {
        u64 a = skeys[tid], b = skeys[tid + 1024];
        #pragma unroll
        for (int k = 2; k <= 32; k <<= 1){
            bool upa = ((tid & k) == 0);
            bool upb = (((tid + 1024) & k) == 0);
            #pragma unroll
            for (int j = k >> 1; j >= 1; j >>= 1){
                a = cmpex(a, j, upa);
                b = cmpex(b, j, upb);
            }
        }
        skeys[tid] = a; skeys[tid + 1024] = b;
        __syncthreads();
        for (int k = 64; k <= K_TOP; k <<= 1){
            for (int j = k >> 1; j >= 32; j >>= 1){
                int ii = ((tid & ~(j-1)) << 1) | (tid & (j-1));
                int pp = ii | j;
                bool up = ((ii & k) == 0);
                u64 x = skeys[ii], y = skeys[pp];
                if ((x > y) == up){ skeys[ii] = y; skeys[pp] = x; }
                __syncthreads();
            }
            a = skeys[tid]; b = skeys[tid + 1024];
            bool upa = ((tid & k) == 0);
            bool upb = (((tid + 1024) & k) == 0);
            #pragma unroll
            for (int j = 16; j >= 1; j >>= 1){
                a = cmpex(a, j, upa);
                b = cmpex(b, j, upb);
            }
            skeys[tid] = a; skeys[tid + 1024] = b;
            __syncthreads();
        }
    }

    // ---- fused decode: skeys still in smem; decode both halves
    u32 lmax = 0u;
    #pragma unroll
    for (int half = 0; half < 2; half++){
        int s = tid + half*1024;
        u64 key = skeys[s];
        g_skeys[img*K_TOP + s] = key;
        u32 hi = (u32)(key >> 32);
        int idx = (int)(key & 0xFFFFFFFFull);
        int il = idx / NFG;
        int c = idx - il*NFG + 1;
        int i = img*N_PROP + il;
        float4 bx;
        decode_box(props4[i], regs4[(size_t)i*NCLS + c], bx);
        g_cand_box[img*K_TOP + s] = bx;
        bool valid = (hi != FILL_HI);
        g_lab[img*K_TOP + s] = (unsigned char)(c | (valid ? 0x80 : 0));
        u32 vb = __ballot_sync(0xFFFFFFFFu, valid);
        if (lane == 0) g_keep[img*64 + (s>>5)] = vb;
        float mx = fmaxf(fmaxf(bx.x, bx.y), fmaxf(bx.z, bx.w));
        u32 mxu = __float_as_uint(mx);
        lmax = lmax > mxu ? lmax : mxu;
    }
    #pragma unroll
    for (int o = 16; o; o >>= 1){
        u32 v = __shfl_xor_sync(0xFFFFFFFFu, lmax, o);
        lmax = lmax > v ? lmax : v;
    }
    if (lane == 0) atomicMax(&g_maxc[img], lmax);
}

// 4 warps/block, one warp per (image,label).
// Suppression-matrix greedy: parallel IoU mask build, then bit-only serial scan.
__global__ void __launch_bounds__(NWARP*32) k_nms(){
    __shared__ u16 mem[NWARP][K_TOP];
    __shared__ u32 smask[NWARP][GCAP][GW];
    __shared__ u32 kb[NWARP][64];
    int wwarp = threadIdx.x >> 5, lane = threadIdx.x & 31;
    int pair = blockIdx.x*NWARP + wwarp;
    int img = pair / NFG;
    int lab = pair - img*NFG + 1;
    u16* memw = mem[wwarp];
    u32* kbw = kb[wwarp];
    float mul = __uint_as_float(g_maxc[img]) + 1.0f;
    float off = (float)lab * mul;
    const u64* labp8 = (const u64*)(g_lab + img*K_TOP);
    const unsigned char* labp = g_lab + img*K_TOP;
    const float4* boxp = g_cand_box + img*K_TOP;

    int g = 0;
    #pragma unroll
    for (int it = 0; it < 8; it++){
        u64 v = labp8[it*32 + lane];
        u32 mymask = 0;
        #pragma unroll
        for (int k = 0; k < 8; k++){
            if ((((u32)(v >> (8*k))) & 0x7Fu) == (u32)lab) mymask |= (1u<<k);
        }
        int mycnt = __popc(mymask);
        int inc = mycnt;
        #pragma unroll
        for (int o=1;o<32;o<<=1){ int x=__shfl_up_sync(0xFFFFFFFFu,inc,o); if(lane>=o) inc+=x; }
        int pos = g + inc - mycnt;
        int tb = (it*32 + lane)*8;
        #pragma unroll
        for (int k = 0; k < 8; k++){
            if (mymask & (1u<<k)) memw[pos++] = (u16)(tb + k);
        }
        g += __shfl_sync(0xFFFFFFFFu, inc, 31);
    }
    __syncwarp();
    int gpad = (g + 31) & ~31;
    for (int ch = 0; ch < gpad; ch += 32){
        int j = ch + lane;
        bool val = (j < g) ? ((labp[memw[j]] & 0x80u) != 0) : false;
        u32 bal = __ballot_sync(0xFFFFFFFFu, val);
        if (lane == 0) kbw[ch>>5] = bal;
    }
    __syncwarp();

    if (g <= GCAP){
        int gwords = (g + 31) >> 5;
        for (int i = lane; i < g; i += 32){
            float4 bi = boxp[memw[i]];
            float ax = bi.x + off, ay = bi.y + off, az = bi.z + off, aw = bi.w + off;
            float aa = (az - ax) * (aw - ay);
            for (int w = 0; w < gwords; w++){
                u32 bits = 0u;
                int j0 = w << 5;
                int jend = min(g, j0 + 32);
                for (int j = max(j0, i+1); j < jend; j++){
                    float4 bj = boxp[memw[j]];
                    float ox = bj.x + off, oy = bj.y + off, oz = bj.z + off, ow = bj.w + off;
                    float ab = (oz - ox) * (ow - oy);
                    float ltx = fmaxf(ax, ox), lty = fmaxf(ay, oy);
                    float rbx = fminf(az, oz), rby = fminf(aw, ow);
                    float wx = fmaxf(rbx - ltx, 0.0f), wy = fmaxf(rby - lty, 0.0f);
                    float inter = wx * wy;
                    float iou = __fdiv_rn(inter, aa + ab - inter);
                    if (iou > NMS_T) bits |= 1u << (j - j0);
                }
                smask[wwarp][i][w] = bits;
            }
        }
        __syncwarp();
        u32 kw = (lane < gwords) ? kbw[lane] : 0u;
        for (int i = 0; i < g; i++){
            u32 wi = __shfl_sync(0xFFFFFFFFu, kw, i >> 5);
            if ((wi >> (i & 31)) & 1u){
                if (lane < gwords) kw &= ~smask[wwarp][i][lane];
            }
        }
        if (lane < gwords) kbw[lane] = kw;
        __syncwarp();
    } else {
        for (int i = 0; i < g; i++){
            if (!((kbw[i>>5] >> (i&31)) & 1u)) continue;
            float4 bi = boxp[memw[i]];
            float ax = bi.x + off, ay = bi.y + off, az = bi.z + off, aw = bi.w + off;
            float aa = (az - ax) * (aw - ay);
            for (int j = i + 1 + lane; j < g; j += 32){
                float4 bj = boxp[memw[j]];
                float ox = bj.x + off, oy = bj.y + off, oz = bj.z + off, ow = bj.w + off;
                float ab = (oz - ox) * (ow - oy);
                float ltx = fmaxf(ax, ox), lty = fmaxf(ay, oy);
                float rbx = fminf(az, oz), rby = fminf(aw, ow);
                float wx = fmaxf(rbx - ltx, 0.0f), wy = fmaxf(rby - lty, 0.0f);
                float inter = wx * wy;
                float iou = __fdiv_rn(inter, aa + ab - inter);
                if (iou > NMS_T) atomicAnd(&kbw[j>>5], ~(1u<<(j&31)));
            }
            __syncwarp();
        }
    }

    for (int j = lane; j < g; j += 32){
        if (!((kbw[j>>5] >> (j&31)) & 1u)){
            int t = memw[j];
            atomicAnd(&g_keep[img*64 + (t>>5)], ~(1u<<(t&31)));
        }
    }
}

__global__ void __launch_bounds__(256) k_emit(float* __restrict__ out){
    __shared__ u32 s_keep[64];
    __shared__ int s_wbase[64];
    __shared__ int s_tot;
    int img = blockIdx.x, tid = threadIdx.x;
    int warp = tid >> 5, lane = tid & 31;
    if (tid < 64) s_keep[tid] = g_keep[img*64 + tid];
    __syncthreads();
    if (warp == 0){
        u32 w0 = s_keep[lane];
        int c0 = __popc(w0), sc0 = c0;
        #pragma unroll
        for (int o=1;o<32;o<<=1){ int v=__shfl_up_sync(0xFFFFFFFFu,sc0,o); if(lane>=o) sc0+=v; }
        s_wbase[lane] = sc0 - c0;
        int tot0 = __shfl_sync(0xFFFFFFFFu, sc0, 31);
        u32 w1 = s_keep[32+lane];
        int c1 = __popc(w1), sc1 = c1;
        #pragma unroll
        for (int o=1;o<32;o<<=1){ int v=__shfl_up_sync(0xFFFFFFFFu,sc1,o); if(lane>=o) sc1+=v; }
        s_wbase[32+lane] = tot0 + sc1 - c1;
        if (lane == 31) s_tot = tot0 + sc1;
    }
    __syncthreads();
    int K = s_tot;
    for (int t2 = tid; t2 < K_TOP; t2 += 256){
        u32 w = s_keep[t2>>5];
        int kbefore = s_wbase[t2>>5] + __popc(w & ((1u<<(t2&31))-1u));
        bool kept = (w >> (t2&31)) & 1u;
        int slot = -1; float osc = 0.0f;
        if (kept){
            if (kbefore < DETS){
                slot = kbefore;
                u32 hi = (u32)(g_skeys[img*K_TOP + t2] >> 32);
                osc = __uint_as_float(~hi & 0x7FFFFFFFu);
            }
        } else if (K < DETS){
            int s2 = K + (t2 - kbefore);
            if (s2 < DETS){ slot = s2; osc = -1.0f; }
        }
        if (slot >= 0){
            ((float4*)out)[img*DETS + slot] = g_cand_box[img*K_TOP + t2];
            out[B_IMG*DETS*4 + img*DETS + slot] = osc;
            out[B_IMG*DETS*5 + img*DETS + slot] = (float)(g_lab[img*K_TOP + t2] & 0x7F);
        }
    }
    __syncthreads();
    if (tid == 0){ g_count[img] = 0; g_maxc[img] = 0u; }
}

extern "C" void kernel_launch(void* const* d_in, const int* in_sizes, int n_in,
                              void* d_out, int out_size) {
    const float*  logits = (const float*)d_in[0];
    const float4* regs4  = (const float4*)d_in[1];
    const float4* props4 = (const float4*)d_in[2];
    float* out = (float*)d_out;
    cudaFuncSetAttribute(k_select, cudaFuncAttributeMaxDynamicSharedMemorySize, SMEM_SEL);
    k_score<<<(B_IMG*N_PROP)/8, 256>>>(logits, regs4, props4);
    k_select<<<B_IMG, 1024, SMEM_SEL>>>(logits, regs4, props4);
    k_nms<<<(B_IMG*NFG)/NWARP, NWARP*32>>>();
    k_emit<<<B_IMG, 256>>>(out);
}